// round 2
// baseline (speedup 1.0000x reference)
#include <cuda_runtime.h>
#include <math.h>

// Problem constants
#define Bb   8
#define Nn   256
#define Dd   512
#define Hh   16
#define Kk   4
#define FFNs 2048
#define Mrows (Bb*Nn)          // 2048 rows for all GEMMs
#define KD   (Kk*Dd)           // 2048

// ---------------- scratch ----------------
__device__ float g_qlin[Mrows*Dd];
__device__ float g_klin[Mrows*Dd];
__device__ float g_vlin[Mrows*Dd];
__device__ float g_msg2[Bb*Nn*KD];
__device__ float g_t1[Mrows*Dd];
__device__ float g_h [Mrows*Dd];
__device__ float g_y [Mrows*Dd];
__device__ float g_t2[Mrows*FFNs];
__device__ float g_f [Mrows*Dd];

// ---------------- GEMM: C = act(A[M,Kdim] @ W[Kdim,Ncols] + bias) ----------------
// BM=128, BN=64, BK=16, 256 threads, 8x4 micro-tile per thread.
// ACT: 0 = none, 1 = silu, 2 = gelu(exact)
template<int ACT>
__global__ void __launch_bounds__(256, 2)
gemm_kernel(const float* __restrict__ A,
            const float* __restrict__ W,
            const float* __restrict__ bias,
            float* __restrict__ C,
            int Kdim, int Ncols)
{
    __shared__ float As[128][17];
    __shared__ float Ws[16][64];     // unpadded: read via float4

    const int tid = threadIdx.x;
    const int tx = tid & 15;         // col group: 4 cols
    const int ty = tid >> 4;         // row group: 8 rows
    const int rowBase = blockIdx.y * 128;
    const int colBase = blockIdx.x * 64;

    float acc[8][4];
    #pragma unroll
    for (int i = 0; i < 8; i++)
        #pragma unroll
        for (int j = 0; j < 4; j++) acc[i][j] = 0.0f;

    for (int k0 = 0; k0 < Kdim; k0 += 16) {
        // A tile: 128x16 = 512 float4, 2 per thread
        #pragma unroll
        for (int i = 0; i < 2; i++) {
            int f = tid + i * 256;
            int r = f >> 2, c4 = (f & 3) * 4;
            float4 v = *reinterpret_cast<const float4*>(&A[(rowBase + r) * Kdim + k0 + c4]);
            As[r][c4+0] = v.x; As[r][c4+1] = v.y; As[r][c4+2] = v.z; As[r][c4+3] = v.w;
        }
        // W tile: 16x64 = 256 float4, 1 per thread
        {
            int r = tid >> 4, c4 = (tid & 15) * 4;
            float4 v = *reinterpret_cast<const float4*>(&W[(k0 + r) * Ncols + colBase + c4]);
            *reinterpret_cast<float4*>(&Ws[r][c4]) = v;
        }
        __syncthreads();

        #pragma unroll
        for (int kkk = 0; kkk < 16; kkk++) {
            float4 bv = *reinterpret_cast<const float4*>(&Ws[kkk][tx*4]);
            float bvv[4] = {bv.x, bv.y, bv.z, bv.w};
            #pragma unroll
            for (int i = 0; i < 8; i++) {
                float a = As[ty*8+i][kkk];
                #pragma unroll
                for (int j = 0; j < 4; j++) acc[i][j] += a * bvv[j];
            }
        }
        __syncthreads();
    }

    #pragma unroll
    for (int i = 0; i < 8; i++) {
        int r = rowBase + ty*8 + i;
        #pragma unroll
        for (int j = 0; j < 4; j++) {
            int cc = colBase + tx*4 + j;
            float v = acc[i][j] + bias[cc];
            if (ACT == 1) {               // silu
                v = v / (1.0f + expf(-v));
            } else if (ACT == 2) {        // exact gelu
                v = 0.5f * v * (1.0f + erff(v * 0.70710678118654752f));
            }
            C[r * Ncols + cc] = v;
        }
    }
}

// ---------------- fused attention ----------------
// grid = (N=256, B*H=128), block = 256 threads. One query row (b,h,n) per
// block; iterates over the 4 distance scales internally (q.k, dist, mask
// loaded once). Writes attn@V directly into the torch-faithful scrambled
// msg2 layout: row = b*256 + (kk*16+h)*4 + (d>>3), col = (d&7)*256 + n.
__global__ void attn_kernel(const float* __restrict__ ql,
                            const float* __restrict__ kl,
                            const float* __restrict__ vl,
                            const float* __restrict__ bias,
                            const int*   __restrict__ mask,
                            const float* __restrict__ dist,
                            const float* __restrict__ dist_bar,
                            float* __restrict__ msg2)
{
    const int n  = blockIdx.x;
    const int bh = blockIdx.y;
    const int b  = bh >> 4;
    const int h  = bh & 15;
    const int t  = threadIdx.x;          // key index m

    __shared__ float shq[32];
    __shared__ float p[256];
    __shared__ float red[256];
    __shared__ float sbar[4];

    if (t < 32)
        shq[t] = ql[(b*Nn + n)*Dd + h*32 + t] * 0.17677669529663687f; // 1/sqrt(32)
    if (t < 4) sbar[t] = dist_bar[t];
    __syncthreads();

    // base score for key m = t (scale-independent part)
    const float* krow = &kl[(b*Nn + t)*Dd + h*32];
    float s_base = 0.0f;
    #pragma unroll
    for (int d4 = 0; d4 < 32; d4 += 4) {
        float4 kv = *reinterpret_cast<const float4*>(&krow[d4]);
        s_base += shq[d4]*kv.x + shq[d4+1]*kv.y + shq[d4+2]*kv.z + shq[d4+3]*kv.w;
    }

    bool pad_ok = (mask[(b*Nn + n)*Nn + t] != 0);
    float dv = -1.0f;                    // negative => always < dist_bar
    if (n > 0 && t > 0)
        dv = dist[(b*(Nn-1) + (n-1))*(Nn-1) + (t-1)];

    const float* brow = &bias[((b*Kk)*Nn + n)*Nn + t];   // + kk*Nn*Nn per scale
    const int d = t & 31;
    const int chunk = t >> 5;

    for (int kk = 0; kk < 4; kk++) {
        float s = s_base + brow[kk * Nn * Nn];
        bool ok = pad_ok && (dv < sbar[kk]);
        if (!ok) s = -1e12f;

        // max
        red[t] = s;
        __syncthreads();
        #pragma unroll
        for (int off = 128; off > 0; off >>= 1) {
            if (t < off) red[t] = fmaxf(red[t], red[t + off]);
            __syncthreads();
        }
        float mx = red[0];
        __syncthreads();

        float ex = __expf(s - mx);
        p[t] = ex;
        red[t] = ex;
        __syncthreads();
        #pragma unroll
        for (int off = 128; off > 0; off >>= 1) {
            if (t < off) red[t] += red[t + off];
            __syncthreads();
        }
        float inv = 1.0f / red[0];
        __syncthreads();

        // attn @ V : thread t handles dim d = t&31, key-chunk = t>>5
        float acc = 0.0f;
        #pragma unroll
        for (int j = 0; j < 32; j++) {
            int mm = chunk*32 + j;
            acc += p[mm] * vl[(b*Nn + mm)*Dd + h*32 + d];
        }
        red[t] = acc;
        __syncthreads();

        if (t < 32) {
            float sum = 0.0f;
            #pragma unroll
            for (int c = 0; c < 8; c++) sum += red[c*32 + t];
            sum *= inv;
            int i = (kk*Hh + h)*4 + (t >> 3);
            int c = (t & 7)*256 + n;
            msg2[(b*Nn + i)*KD + c] = sum;
        }
        __syncthreads();
    }
}

// ---------------- residual add + LayerNorm (D = 512) ----------------
__global__ void ln_kernel(const float* __restrict__ a,
                          const float* __restrict__ res,
                          const float* __restrict__ g,
                          const float* __restrict__ be,
                          float* __restrict__ out)
{
    const int row = blockIdx.x;
    const int t = threadIdx.x;
    __shared__ float red[256];

    float v0 = a[row*Dd + t]       + res[row*Dd + t];
    float v1 = a[row*Dd + 256 + t] + res[row*Dd + 256 + t];

    red[t] = v0 + v1;
    __syncthreads();
    #pragma unroll
    for (int off = 128; off > 0; off >>= 1) {
        if (t < off) red[t] += red[t + off];
        __syncthreads();
    }
    float mean = red[0] * (1.0f / 512.0f);
    __syncthreads();

    float d0 = v0 - mean, d1 = v1 - mean;
    red[t] = d0*d0 + d1*d1;
    __syncthreads();
    #pragma unroll
    for (int off = 128; off > 0; off >>= 1) {
        if (t < off) red[t] += red[t + off];
        __syncthreads();
    }
    float var = red[0] * (1.0f / 512.0f);
    float rstd = rsqrtf(var + 1e-6f);

    out[row*Dd + t]       = d0 * rstd * g[t]       + be[t];
    out[row*Dd + 256 + t] = d1 * rstd * g[t + 256] + be[t + 256];
}

// ---------------- launch ----------------
extern "C" void kernel_launch(void* const* d_in, const int* in_sizes, int n_in,
                              void* d_out, int out_size)
{
    const float* x         = (const float*)d_in[0];
    const float* dist      = (const float*)d_in[1];
    const float* dist_bar  = (const float*)d_in[2];
    const float* attn_bias = (const float*)d_in[3];
    const int*   mask      = (const int*)  d_in[4];
    // d_in[5] = num_heads (compile-time)
    const float* Wq = (const float*)d_in[6],  *bq = (const float*)d_in[7];
    const float* Wk = (const float*)d_in[8],  *bk = (const float*)d_in[9];
    const float* Wv = (const float*)d_in[10], *bv = (const float*)d_in[11];
    const float* W1 = (const float*)d_in[12], *b1 = (const float*)d_in[13];
    const float* W2 = (const float*)d_in[14], *b2 = (const float*)d_in[15];
    const float* g1 = (const float*)d_in[16], *be1 = (const float*)d_in[17];
    const float* Wf1 = (const float*)d_in[18], *bf1 = (const float*)d_in[19];
    const float* Wf2 = (const float*)d_in[20], *bf2 = (const float*)d_in[21];
    const float* g2 = (const float*)d_in[22], *be2 = (const float*)d_in[23];
    float* out = (float*)d_out;

    float *qlin, *klin, *vlin, *msg2, *t1, *hb, *yb, *t2, *fb;
    cudaGetSymbolAddress((void**)&qlin, g_qlin);
    cudaGetSymbolAddress((void**)&klin, g_klin);
    cudaGetSymbolAddress((void**)&vlin, g_vlin);
    cudaGetSymbolAddress((void**)&msg2, g_msg2);
    cudaGetSymbolAddress((void**)&t1,   g_t1);
    cudaGetSymbolAddress((void**)&hb,   g_h);
    cudaGetSymbolAddress((void**)&yb,   g_y);
    cudaGetSymbolAddress((void**)&t2,   g_t2);
    cudaGetSymbolAddress((void**)&fb,   g_f);

    dim3 blk(256);
    dim3 g512(Dd/64,  Mrows/128);   // (8, 16)
    dim3 gFFN(FFNs/64, Mrows/128);  // (32, 16)

    gemm_kernel<0><<<g512, blk>>>(x, Wq, bq, qlin, Dd, Dd);
    gemm_kernel<0><<<g512, blk>>>(x, Wk, bk, klin, Dd, Dd);
    gemm_kernel<0><<<g512, blk>>>(x, Wv, bv, vlin, Dd, Dd);

    dim3 ga(Nn, Bb*Hh);             // (256, 128)
    attn_kernel<<<ga, blk>>>(qlin, klin, vlin, attn_bias, mask, dist, dist_bar, msg2);

    gemm_kernel<1><<<g512, blk>>>(msg2, W1, b1, t1, KD, Dd);
    gemm_kernel<0><<<g512, blk>>>(t1,   W2, b2, hb, Dd, Dd);
    ln_kernel<<<Mrows, blk>>>(hb, x, g1, be1, yb);

    gemm_kernel<2><<<gFFN, blk>>>(yb, Wf1, bf1, t2, Dd, FFNs);
    gemm_kernel<0><<<g512, blk>>>(t2, Wf2, bf2, fb, FFNs, Dd);
    ln_kernel<<<Mrows, blk>>>(fb, yb, g2, be2, out);
}

// round 6
// speedup vs baseline: 2.1036x; 2.1036x over previous
#include <cuda_runtime.h>
#include <math.h>
#include <stdint.h>

// Problem constants
#define Bb   8
#define Nn   256
#define Dd   512
#define Hh   16
#define Kk   4
#define FFNs 2048
#define Mrows (Bb*Nn)          // 2048 rows for all GEMMs
#define KD   (Kk*Dd)           // 2048

// ---------------- scratch ----------------
__device__ float g_qlin[Mrows*Dd];
__device__ float g_klin[Mrows*Dd];
__device__ float g_vlin[Mrows*Dd];
__device__ float g_msg2[Bb*Nn*KD];
__device__ float g_t1[Mrows*Dd];
__device__ float g_h [Mrows*Dd];
__device__ float g_y [Mrows*Dd];
__device__ float g_t2[Mrows*FFNs];
__device__ float g_f [Mrows*Dd];

// ---------------- fp32 FFMA GEMM (kept for QKV, precision headroom) ----------------
// BM=128, BN=64, BK=16, 256 threads, 8x4 micro-tile per thread.
template<int ACT>
__global__ void __launch_bounds__(256, 2)
gemm_kernel(const float* __restrict__ A,
            const float* __restrict__ W,
            const float* __restrict__ bias,
            float* __restrict__ C,
            int Kdim, int Ncols)
{
    __shared__ float As[128][17];
    __shared__ float Ws[16][64];

    const int tid = threadIdx.x;
    const int tx = tid & 15;
    const int ty = tid >> 4;
    const int rowBase = blockIdx.y * 128;
    const int colBase = blockIdx.x * 64;

    float acc[8][4];
    #pragma unroll
    for (int i = 0; i < 8; i++)
        #pragma unroll
        for (int j = 0; j < 4; j++) acc[i][j] = 0.0f;

    for (int k0 = 0; k0 < Kdim; k0 += 16) {
        #pragma unroll
        for (int i = 0; i < 2; i++) {
            int f = tid + i * 256;
            int r = f >> 2, c4 = (f & 3) * 4;
            float4 v = *reinterpret_cast<const float4*>(&A[(rowBase + r) * Kdim + k0 + c4]);
            As[r][c4+0] = v.x; As[r][c4+1] = v.y; As[r][c4+2] = v.z; As[r][c4+3] = v.w;
        }
        {
            int r = tid >> 4, c4 = (tid & 15) * 4;
            float4 v = *reinterpret_cast<const float4*>(&W[(k0 + r) * Ncols + colBase + c4]);
            *reinterpret_cast<float4*>(&Ws[r][c4]) = v;
        }
        __syncthreads();

        #pragma unroll
        for (int kkk = 0; kkk < 16; kkk++) {
            float4 bv = *reinterpret_cast<const float4*>(&Ws[kkk][tx*4]);
            float bvv[4] = {bv.x, bv.y, bv.z, bv.w};
            #pragma unroll
            for (int i = 0; i < 8; i++) {
                float a = As[ty*8+i][kkk];
                #pragma unroll
                for (int j = 0; j < 4; j++) acc[i][j] += a * bvv[j];
            }
        }
        __syncthreads();
    }

    #pragma unroll
    for (int i = 0; i < 8; i++) {
        int r = rowBase + ty*8 + i;
        #pragma unroll
        for (int j = 0; j < 4; j++) {
            int cc = colBase + tx*4 + j;
            float v = acc[i][j] + bias[cc];
            if (ACT == 1) {
                v = v / (1.0f + expf(-v));
            } else if (ACT == 2) {
                v = 0.5f * v * (1.0f + erff(v * 0.70710678118654752f));
            }
            C[r * Ncols + cc] = v;
        }
    }
}

// ---------------- tf32 tensor-core GEMM (mma.sync.m16n8k8) ----------------
// BM=128, BN=64, BK=16, 256 threads = 8 warps (4 in M x 2 in N).
// Warp tile 32x32 = 2 M-atoms x 4 N-atoms of m16n8k8. fp32 accumulate.
// Operands rounded to tf32 (cvt.rna) at smem staging time.
__device__ __forceinline__ uint32_t f2tf32(float x) {
    uint32_t u;
    asm("cvt.rna.tf32.f32 %0, %1;" : "=r"(u) : "f"(x));
    return u;
}

template<int ACT>
__global__ void __launch_bounds__(256, 2)
gemm_tf32_kernel(const float* __restrict__ A,
                 const float* __restrict__ W,
                 const float* __restrict__ bias,
                 float* __restrict__ C,
                 int Kdim, int Ncols)
{
    __shared__ uint32_t As[128][17];   // tf32 bits, pad 17
    __shared__ uint32_t Ws[16][68];    // tf32 bits, pad 68 (kills B-frag conflicts)

    const int tid  = threadIdx.x;
    const int warp = tid >> 5;
    const int lane = tid & 31;
    const int wm = warp & 3;           // 4 warps in M
    const int wn = warp >> 2;          // 2 warps in N
    const int g  = lane >> 2;          // group id (0..7)
    const int tg = lane & 3;           // thread in group (0..3)

    const int rowBase = blockIdx.y * 128;
    const int colBase = blockIdx.x * 64;

    float c[2][4][4];
    #pragma unroll
    for (int i = 0; i < 2; i++)
        #pragma unroll
        for (int j = 0; j < 4; j++)
            #pragma unroll
            for (int q = 0; q < 4; q++) c[i][j][q] = 0.0f;

    for (int k0 = 0; k0 < Kdim; k0 += 16) {
        // stage A: 128x16 = 512 float4, 2 per thread, convert to tf32
        #pragma unroll
        for (int i = 0; i < 2; i++) {
            int f = tid + i * 256;
            int r = f >> 2, c4 = (f & 3) * 4;
            float4 v = *reinterpret_cast<const float4*>(&A[(rowBase + r) * Kdim + k0 + c4]);
            As[r][c4+0] = f2tf32(v.x); As[r][c4+1] = f2tf32(v.y);
            As[r][c4+2] = f2tf32(v.z); As[r][c4+3] = f2tf32(v.w);
        }
        // stage W: 16x64 = 256 float4, 1 per thread
        {
            int r = tid >> 4, c4 = (tid & 15) * 4;
            float4 v = *reinterpret_cast<const float4*>(&W[(k0 + r) * Ncols + colBase + c4]);
            Ws[r][c4+0] = f2tf32(v.x); Ws[r][c4+1] = f2tf32(v.y);
            Ws[r][c4+2] = f2tf32(v.z); Ws[r][c4+3] = f2tf32(v.w);
        }
        __syncthreads();

        #pragma unroll
        for (int ks = 0; ks < 16; ks += 8) {
            // A fragments: 2 M-atoms x 4 regs
            uint32_t a[2][4];
            #pragma unroll
            for (int ma = 0; ma < 2; ma++) {
                int r = wm*32 + ma*16;
                a[ma][0] = As[r + g    ][ks + tg    ];
                a[ma][1] = As[r + g + 8][ks + tg    ];
                a[ma][2] = As[r + g    ][ks + tg + 4];
                a[ma][3] = As[r + g + 8][ks + tg + 4];
            }
            // B fragments: 4 N-atoms x 2 regs (col-major frag: b0=(k=tg,n), b1=(k=tg+4,n))
            uint32_t bfr[4][2];
            #pragma unroll
            for (int na = 0; na < 4; na++) {
                int n = wn*32 + na*8 + g;
                bfr[na][0] = Ws[ks + tg    ][n];
                bfr[na][1] = Ws[ks + tg + 4][n];
            }
            #pragma unroll
            for (int ma = 0; ma < 2; ma++)
                #pragma unroll
                for (int na = 0; na < 4; na++) {
                    asm volatile(
                        "mma.sync.aligned.m16n8k8.row.col.f32.tf32.tf32.f32 "
                        "{%0,%1,%2,%3}, {%4,%5,%6,%7}, {%8,%9}, {%0,%1,%2,%3};"
                        : "+f"(c[ma][na][0]), "+f"(c[ma][na][1]),
                          "+f"(c[ma][na][2]), "+f"(c[ma][na][3])
                        : "r"(a[ma][0]), "r"(a[ma][1]), "r"(a[ma][2]), "r"(a[ma][3]),
                          "r"(bfr[na][0]), "r"(bfr[na][1]));
                }
        }
        __syncthreads();
    }

    // epilogue: c0:(g, 2tg) c1:(g, 2tg+1) c2:(g+8, 2tg) c3:(g+8, 2tg+1)
    #pragma unroll
    for (int ma = 0; ma < 2; ma++) {
        int row0 = rowBase + wm*32 + ma*16 + g;
        #pragma unroll
        for (int na = 0; na < 4; na++) {
            int col = colBase + wn*32 + na*8 + tg*2;
            float b0 = bias[col], b1 = bias[col+1];
            float v00 = c[ma][na][0] + b0, v01 = c[ma][na][1] + b1;
            float v10 = c[ma][na][2] + b0, v11 = c[ma][na][3] + b1;
            if (ACT == 1) {
                v00 = v00 / (1.0f + expf(-v00)); v01 = v01 / (1.0f + expf(-v01));
                v10 = v10 / (1.0f + expf(-v10)); v11 = v11 / (1.0f + expf(-v11));
            } else if (ACT == 2) {
                const float is2 = 0.70710678118654752f;
                v00 = 0.5f*v00*(1.0f+erff(v00*is2)); v01 = 0.5f*v01*(1.0f+erff(v01*is2));
                v10 = 0.5f*v10*(1.0f+erff(v10*is2)); v11 = 0.5f*v11*(1.0f+erff(v11*is2));
            }
            C[ row0      * Ncols + col    ] = v00;
            C[ row0      * Ncols + col + 1] = v01;
            C[(row0 + 8) * Ncols + col    ] = v10;
            C[(row0 + 8) * Ncols + col + 1] = v11;
        }
    }
}

// ---------------- fused multi-scale attention, tile-resident K/V ----------------
// grid = (B*H = 128, N/32 = 8), block = 256 threads (8 warps).
// Stages K/V tiles (256x32, XOR-swizzled) per (b,h); warp-per-query with
// shfl-only reductions; p for 4 scales packed float4-per-key; single AV pass.
// Scatters into the torch-faithful scrambled msg2 layout:
//   row = b*256 + (kk*16+h)*4 + (d>>3), col = (d&7)*256 + n.
__global__ void __launch_bounds__(256, 2)
attn_kernel(const float* __restrict__ ql,
            const float* __restrict__ kl,
            const float* __restrict__ vl,
            const float* __restrict__ bias,
            const int*   __restrict__ mask,
            const float* __restrict__ dist,
            const float* __restrict__ dist_bar,
            float* __restrict__ msg2)
{
    extern __shared__ float smem[];
    float* Ksm = smem;                 // [256][32] swizzled: col = d ^ (m&31)
    float* Vsm = smem + 8192;          // [256][32] swizzled
    const int tid  = threadIdx.x;
    const int warp = tid >> 5;
    const int lane = tid & 31;
    float* Psm = smem + 16384 + warp * 1024;   // per-warp [256 keys][4 scales]

    const int bh = blockIdx.x;
    const int b  = bh >> 4;
    const int h  = bh & 15;
    const int n0 = blockIdx.y * 32;

    {
        const float* kbase = &kl[(b*Nn)*Dd + h*32];
        const float* vbase = &vl[(b*Nn)*Dd + h*32];
        #pragma unroll
        for (int it = 0; it < 32; it++) {
            int idx = tid + it * 256;
            int m = idx >> 5, d = idx & 31;
            int c = d ^ (m & 31);
            Ksm[m*32 + c] = kbase[m*Dd + d];
            Vsm[m*32 + c] = vbase[m*Dd + d];
        }
    }
    float bar0 = dist_bar[0], bar1 = dist_bar[1], bar2 = dist_bar[2], bar3 = dist_bar[3];
    __syncthreads();

    for (int qi = 0; qi < 4; qi++) {
        const int n = n0 + qi*8 + warp;

        float qreg = ql[(b*Nn + n)*Dd + h*32 + lane] * 0.17677669529663687f;

        unsigned okbits = 0;
        float dv[8];
        const int*   mrow = &mask[(b*Nn + n)*Nn];
        const float* drow = (n > 0) ? &dist[(b*(Nn-1) + (n-1))*(Nn-1)] : 0;
        #pragma unroll
        for (int i = 0; i < 8; i++) {
            int m = 32*i + lane;
            if (mrow[m] != 0) okbits |= (1u << i);
            dv[i] = (n > 0 && m > 0) ? drow[m-1] : -1.0f;
        }

        float sb[8];
        #pragma unroll
        for (int i = 0; i < 8; i++) sb[i] = 0.0f;
        #pragma unroll
        for (int d = 0; d < 32; d++) {
            float qd = __shfl_sync(0xffffffffu, qreg, d);
            int cc = d ^ lane;
            #pragma unroll
            for (int i = 0; i < 8; i++)
                sb[i] += qd * Ksm[(32*i + lane)*32 + cc];
        }

        const float* bbase = &bias[((b*Kk)*Nn + n)*Nn];
        #pragma unroll
        for (int kk = 0; kk < 4; kk++) {
            float bar = (kk == 0) ? bar0 : (kk == 1) ? bar1 : (kk == 2) ? bar2 : bar3;
            const float* brow = bbase + kk*Nn*Nn;
            float s[8];
            float mx = -1e30f;
            #pragma unroll
            for (int i = 0; i < 8; i++) {
                int m = 32*i + lane;
                float sv = sb[i] + brow[m];
                bool ok = ((okbits >> i) & 1u) && (dv[i] < bar);
                s[i] = ok ? sv : -1e12f;
                mx = fmaxf(mx, s[i]);
            }
            #pragma unroll
            for (int off = 16; off > 0; off >>= 1)
                mx = fmaxf(mx, __shfl_xor_sync(0xffffffffu, mx, off));
            float sum = 0.0f;
            #pragma unroll
            for (int i = 0; i < 8; i++) {
                s[i] = __expf(s[i] - mx);
                sum += s[i];
            }
            #pragma unroll
            for (int off = 16; off > 0; off >>= 1)
                sum += __shfl_xor_sync(0xffffffffu, sum, off);
            float inv = 1.0f / sum;
            #pragma unroll
            for (int i = 0; i < 8; i++)
                Psm[(32*i + lane)*4 + kk] = s[i] * inv;
        }
        __syncwarp();

        float a0 = 0.0f, a1 = 0.0f, a2 = 0.0f, a3 = 0.0f;
        #pragma unroll 4
        for (int m = 0; m < 256; m++) {
            float4 pv = *reinterpret_cast<const float4*>(&Psm[m*4]);
            float v = Vsm[m*32 + (lane ^ (m & 31))];
            a0 += pv.x * v; a1 += pv.y * v; a2 += pv.z * v; a3 += pv.w * v;
        }

        {
            int rsub = h*4 + (lane >> 3);
            int col  = (lane & 7)*256 + n;
            float av[4] = {a0, a1, a2, a3};
            #pragma unroll
            for (int kk = 0; kk < 4; kk++) {
                int row = kk*64 + rsub;
                msg2[(b*Nn + row)*KD + col] = av[kk];
            }
        }
        __syncwarp();
    }
}

// ---------------- residual add + LayerNorm (D = 512) ----------------
__global__ void ln_kernel(const float* __restrict__ a,
                          const float* __restrict__ res,
                          const float* __restrict__ g,
                          const float* __restrict__ be,
                          float* __restrict__ out)
{
    const int row = blockIdx.x;
    const int t = threadIdx.x;
    __shared__ float red[256];

    float v0 = a[row*Dd + t]       + res[row*Dd + t];
    float v1 = a[row*Dd + 256 + t] + res[row*Dd + 256 + t];

    red[t] = v0 + v1;
    __syncthreads();
    #pragma unroll
    for (int off = 128; off > 0; off >>= 1) {
        if (t < off) red[t] += red[t + off];
        __syncthreads();
    }
    float mean = red[0] * (1.0f / 512.0f);
    __syncthreads();

    float d0 = v0 - mean, d1 = v1 - mean;
    red[t] = d0*d0 + d1*d1;
    __syncthreads();
    #pragma unroll
    for (int off = 128; off > 0; off >>= 1) {
        if (t < off) red[t] += red[t + off];
        __syncthreads();
    }
    float var = red[0] * (1.0f / 512.0f);
    float rstd = rsqrtf(var + 1e-6f);

    out[row*Dd + t]       = d0 * rstd * g[t]       + be[t];
    out[row*Dd + 256 + t] = d1 * rstd * g[t + 256] + be[t + 256];
}

// ---------------- launch ----------------
extern "C" void kernel_launch(void* const* d_in, const int* in_sizes, int n_in,
                              void* d_out, int out_size)
{
    const float* x         = (const float*)d_in[0];
    const float* dist      = (const float*)d_in[1];
    const float* dist_bar  = (const float*)d_in[2];
    const float* attn_bias = (const float*)d_in[3];
    const int*   mask      = (const int*)  d_in[4];
    // d_in[5] = num_heads (compile-time)
    const float* Wq = (const float*)d_in[6],  *bq = (const float*)d_in[7];
    const float* Wk = (const float*)d_in[8],  *bk = (const float*)d_in[9];
    const float* Wv = (const float*)d_in[10], *bv = (const float*)d_in[11];
    const float* W1 = (const float*)d_in[12], *b1 = (const float*)d_in[13];
    const float* W2 = (const float*)d_in[14], *b2 = (const float*)d_in[15];
    const float* g1 = (const float*)d_in[16], *be1 = (const float*)d_in[17];
    const float* Wf1 = (const float*)d_in[18], *bf1 = (const float*)d_in[19];
    const float* Wf2 = (const float*)d_in[20], *bf2 = (const float*)d_in[21];
    const float* g2 = (const float*)d_in[22], *be2 = (const float*)d_in[23];
    float* out = (float*)d_out;

    float *qlin, *klin, *vlin, *msg2, *t1, *hb, *yb, *t2, *fb;
    cudaGetSymbolAddress((void**)&qlin, g_qlin);
    cudaGetSymbolAddress((void**)&klin, g_klin);
    cudaGetSymbolAddress((void**)&vlin, g_vlin);
    cudaGetSymbolAddress((void**)&msg2, g_msg2);
    cudaGetSymbolAddress((void**)&t1,   g_t1);
    cudaGetSymbolAddress((void**)&hb,   g_h);
    cudaGetSymbolAddress((void**)&yb,   g_y);
    cudaGetSymbolAddress((void**)&t2,   g_t2);
    cudaGetSymbolAddress((void**)&fb,   g_f);

    dim3 blk(256);
    dim3 g512(Dd/64,  Mrows/128);   // (8, 16)
    dim3 gFFN(FFNs/64, Mrows/128);  // (32, 16)

    // QKV: fp32 FFMA (precision headroom for attention)
    gemm_kernel<0><<<g512, blk>>>(x, Wq, bq, qlin, Dd, Dd);
    gemm_kernel<0><<<g512, blk>>>(x, Wk, bk, klin, Dd, Dd);
    gemm_kernel<0><<<g512, blk>>>(x, Wv, bv, vlin, Dd, Dd);

    // fused attention: 96KB dynamic smem (K 32KB + V 32KB + 8 warps x 4KB p)
    const int ATTN_SMEM = 98304;
    cudaFuncSetAttribute(attn_kernel,
                         cudaFuncAttributeMaxDynamicSharedMemorySize, ATTN_SMEM);
    dim3 ga(Bb*Hh, Nn/32);          // (128, 8)
    attn_kernel<<<ga, blk, ATTN_SMEM>>>(qlin, klin, vlin, attn_bias, mask,
                                        dist, dist_bar, msg2);

    // big GEMMs: tf32 tensor cores
    gemm_tf32_kernel<1><<<g512, blk>>>(msg2, W1, b1, t1, KD, Dd);
    gemm_tf32_kernel<0><<<g512, blk>>>(t1,   W2, b2, hb, Dd, Dd);
    ln_kernel<<<Mrows, blk>>>(hb, x, g1, be1, yb);

    gemm_tf32_kernel<2><<<gFFN, blk>>>(yb, Wf1, bf1, t2, Dd, FFNs);
    gemm_tf32_kernel<0><<<g512, blk>>>(t2, Wf2, bf2, fb, FFNs, Dd);
    ln_kernel<<<Mrows, blk>>>(fb, yb, g2, be2, out);
}

// round 12
// speedup vs baseline: 2.3739x; 1.1285x over previous
#include <cuda_runtime.h>
#include <math.h>
#include <stdint.h>

// Problem constants
#define Bb   8
#define Nn   256
#define Dd   512
#define Hh   16
#define Kk   4
#define FFNs 2048
#define Mrows (Bb*Nn)          // 2048
#define KD   (Kk*Dd)           // 2048

// ---------------- scratch ----------------
__device__ float g_qlin[Mrows*Dd];
__device__ float g_klin[Mrows*Dd];
__device__ float g_vlin[Mrows*Dd];
__device__ float g_msg2[Mrows*KD];
__device__ float g_t1[Mrows*Dd];
__device__ float g_h [Mrows*Dd];
__device__ float g_y [Mrows*Dd];
__device__ float g_t2[Mrows*FFNs];
__device__ float g_f [Mrows*Dd];

// ---------------- fp32 FFMA GEMM (QKV only — precision headroom) ----------------
// BM=128, BN=64, BK=16, 256 threads, 8x4 micro-tile per thread.
template<int ACT>
__global__ void __launch_bounds__(256, 2)
gemm_kernel(const float* __restrict__ A,
            const float* __restrict__ W,
            const float* __restrict__ bias,
            float* __restrict__ C,
            int Kdim, int Ncols)
{
    __shared__ float As[128][17];
    __shared__ float Ws[16][64];

    const int tid = threadIdx.x;
    const int tx = tid & 15;
    const int ty = tid >> 4;
    const int rowBase = blockIdx.y * 128;
    const int colBase = blockIdx.x * 64;

    float acc[8][4];
    #pragma unroll
    for (int i = 0; i < 8; i++)
        #pragma unroll
        for (int j = 0; j < 4; j++) acc[i][j] = 0.0f;

    for (int k0 = 0; k0 < Kdim; k0 += 16) {
        #pragma unroll
        for (int i = 0; i < 2; i++) {
            int f = tid + i * 256;
            int r = f >> 2, c4 = (f & 3) * 4;
            float4 v = *reinterpret_cast<const float4*>(&A[(rowBase + r) * Kdim + k0 + c4]);
            As[r][c4+0] = v.x; As[r][c4+1] = v.y; As[r][c4+2] = v.z; As[r][c4+3] = v.w;
        }
        {
            int r = tid >> 4, c4 = (tid & 15) * 4;
            float4 v = *reinterpret_cast<const float4*>(&W[(k0 + r) * Ncols + colBase + c4]);
            *reinterpret_cast<float4*>(&Ws[r][c4]) = v;
        }
        __syncthreads();

        #pragma unroll
        for (int kkk = 0; kkk < 16; kkk++) {
            float4 bv = *reinterpret_cast<const float4*>(&Ws[kkk][tx*4]);
            float bvv[4] = {bv.x, bv.y, bv.z, bv.w};
            #pragma unroll
            for (int i = 0; i < 8; i++) {
                float a = As[ty*8+i][kkk];
                #pragma unroll
                for (int j = 0; j < 4; j++) acc[i][j] += a * bvv[j];
            }
        }
        __syncthreads();
    }

    #pragma unroll
    for (int i = 0; i < 8; i++) {
        int r = rowBase + ty*8 + i;
        #pragma unroll
        for (int j = 0; j < 4; j++) {
            int cc = colBase + tx*4 + j;
            C[r * Ncols + cc] = acc[i][j] + bias[cc];
        }
    }
}

// ---------------- tf32 tensor-core GEMM, software-pipelined ----------------
// BM=128, BN=64, BK=16, 256 threads = 8 warps (4 M x 2 N), warp tile 32x32.
// Double-buffered smem; per iter: issue next-tile LDG, run MMAs on current
// buffer, then CVT+STS the in-flight data (overlaps global latency with MMA).
__device__ __forceinline__ uint32_t f2tf32(float x) {
    uint32_t u;
    asm("cvt.rna.tf32.f32 %0, %1;" : "=r"(u) : "f"(x));
    return u;
}

template<int ACT>
__global__ void __launch_bounds__(256, 2)
gemm_tf32_kernel(const float* __restrict__ A,
                 const float* __restrict__ W,
                 const float* __restrict__ bias,
                 float* __restrict__ C,
                 int Kdim, int Ncols)
{
    __shared__ uint32_t As[2][128][17];
    __shared__ uint32_t Ws[2][16][68];

    const int tid  = threadIdx.x;
    const int warp = tid >> 5;
    const int lane = tid & 31;
    const int wm = warp & 3;
    const int wn = warp >> 2;
    const int g  = lane >> 2;
    const int tg = lane & 3;

    const int rowBase = blockIdx.y * 128;
    const int colBase = blockIdx.x * 64;

    // fixed per-thread staging coordinates
    const int a0r = tid >> 2,          a0c = (tid & 3) * 4;
    const int a1r = (tid + 256) >> 2,  a1c = a0c;
    const int wr  = tid >> 4,          wc  = (tid & 15) * 4;

    float c[2][4][4];
    #pragma unroll
    for (int i = 0; i < 2; i++)
        #pragma unroll
        for (int j = 0; j < 4; j++)
            #pragma unroll
            for (int q = 0; q < 4; q++) c[i][j][q] = 0.0f;

    float4 va0, va1, vw;
    auto gload = [&](int k0) {
        va0 = *reinterpret_cast<const float4*>(&A[(rowBase + a0r) * Kdim + k0 + a0c]);
        va1 = *reinterpret_cast<const float4*>(&A[(rowBase + a1r) * Kdim + k0 + a1c]);
        vw  = *reinterpret_cast<const float4*>(&W[(k0 + wr) * Ncols + colBase + wc]);
    };
    auto sstore = [&](int buf) {
        As[buf][a0r][a0c+0] = f2tf32(va0.x); As[buf][a0r][a0c+1] = f2tf32(va0.y);
        As[buf][a0r][a0c+2] = f2tf32(va0.z); As[buf][a0r][a0c+3] = f2tf32(va0.w);
        As[buf][a1r][a1c+0] = f2tf32(va1.x); As[buf][a1r][a1c+1] = f2tf32(va1.y);
        As[buf][a1r][a1c+2] = f2tf32(va1.z); As[buf][a1r][a1c+3] = f2tf32(va1.w);
        Ws[buf][wr][wc+0] = f2tf32(vw.x); Ws[buf][wr][wc+1] = f2tf32(vw.y);
        Ws[buf][wr][wc+2] = f2tf32(vw.z); Ws[buf][wr][wc+3] = f2tf32(vw.w);
    };

    const int nIter = Kdim >> 4;
    gload(0);
    sstore(0);
    __syncthreads();

    for (int it = 0; it < nIter; it++) {
        const int buf = it & 1;
        if (it + 1 < nIter) gload((it + 1) << 4);     // LDG in flight during MMAs

        #pragma unroll
        for (int ks = 0; ks < 16; ks += 8) {
            uint32_t a[2][4];
            #pragma unroll
            for (int ma = 0; ma < 2; ma++) {
                int r = wm*32 + ma*16;
                a[ma][0] = As[buf][r + g    ][ks + tg    ];
                a[ma][1] = As[buf][r + g + 8][ks + tg    ];
                a[ma][2] = As[buf][r + g    ][ks + tg + 4];
                a[ma][3] = As[buf][r + g + 8][ks + tg + 4];
            }
            uint32_t bfr[4][2];
            #pragma unroll
            for (int na = 0; na < 4; na++) {
                int n = wn*32 + na*8 + g;
                bfr[na][0] = Ws[buf][ks + tg    ][n];
                bfr[na][1] = Ws[buf][ks + tg + 4][n];
            }
            #pragma unroll
            for (int ma = 0; ma < 2; ma++)
                #pragma unroll
                for (int na = 0; na < 4; na++) {
                    asm volatile(
                        "mma.sync.aligned.m16n8k8.row.col.f32.tf32.tf32.f32 "
                        "{%0,%1,%2,%3}, {%4,%5,%6,%7}, {%8,%9}, {%0,%1,%2,%3};"
                        : "+f"(c[ma][na][0]), "+f"(c[ma][na][1]),
                          "+f"(c[ma][na][2]), "+f"(c[ma][na][3])
                        : "r"(a[ma][0]), "r"(a[ma][1]), "r"(a[ma][2]), "r"(a[ma][3]),
                          "r"(bfr[na][0]), "r"(bfr[na][1]));
                }
        }

        if (it + 1 < nIter) sstore(buf ^ 1);          // stalls on LDG only here
        __syncthreads();
    }

    // epilogue: c0:(g,2tg) c1:(g,2tg+1) c2:(g+8,2tg) c3:(g+8,2tg+1)
    #pragma unroll
    for (int ma = 0; ma < 2; ma++) {
        int row0 = rowBase + wm*32 + ma*16 + g;
        #pragma unroll
        for (int na = 0; na < 4; na++) {
            int col = colBase + wn*32 + na*8 + tg*2;
            float b0 = bias[col], b1 = bias[col+1];
            float v00 = c[ma][na][0] + b0, v01 = c[ma][na][1] + b1;
            float v10 = c[ma][na][2] + b0, v11 = c[ma][na][3] + b1;
            if (ACT == 1) {
                v00 = v00 / (1.0f + expf(-v00)); v01 = v01 / (1.0f + expf(-v01));
                v10 = v10 / (1.0f + expf(-v10)); v11 = v11 / (1.0f + expf(-v11));
            } else if (ACT == 2) {
                const float is2 = 0.70710678118654752f;
                v00 = 0.5f*v00*(1.0f+erff(v00*is2)); v01 = 0.5f*v01*(1.0f+erff(v01*is2));
                v10 = 0.5f*v10*(1.0f+erff(v10*is2)); v11 = 0.5f*v11*(1.0f+erff(v11*is2));
            }
            C[ row0      * Ncols + col    ] = v00;
            C[ row0      * Ncols + col + 1] = v01;
            C[(row0 + 8) * Ncols + col    ] = v10;
            C[(row0 + 8) * Ncols + col + 1] = v11;
        }
    }
}

// ---------------- fused multi-scale attention ----------------
// grid = (B*H = 128, N/32 = 8), block = 256 (8 warps). K swizzled, V plain
// (AV reads naturally conflict-free). Warp-per-query, shfl-only softmax,
// p packed float4-per-key, single AV pass over 4 scales. Scatter into the
// torch-faithful scrambled msg2 layout:
//   row = b*256 + (kk*16+h)*4 + (d>>3), col = (d&7)*256 + n.
__global__ void __launch_bounds__(256, 2)
attn_kernel(const float* __restrict__ ql,
            const float* __restrict__ kl,
            const float* __restrict__ vl,
            const float* __restrict__ bias,
            const int*   __restrict__ mask,
            const float* __restrict__ dist,
            const float* __restrict__ dist_bar,
            float* __restrict__ msg2)
{
    extern __shared__ float smemf[];
    float* Ksm = smemf;                // [256][32] swizzled: col = d ^ (m&31)
    float* Vsm = smemf + 8192;         // [256][32] PLAIN layout
    const int tid  = threadIdx.x;
    const int warp = tid >> 5;
    const int lane = tid & 31;
    float* Psm = smemf + 16384 + warp * 1024;   // per-warp [256 keys][4 scales]

    const int bh = blockIdx.x;
    const int b  = bh >> 4;
    const int h  = bh & 15;
    const int n0 = blockIdx.y * 32;

    {
        const float* kbase = &kl[(b*Nn)*Dd + h*32];
        const float* vbase = &vl[(b*Nn)*Dd + h*32];
        #pragma unroll
        for (int it = 0; it < 32; it++) {
            int idx = tid + it * 256;
            int m = idx >> 5, d = idx & 31;
            Ksm[m*32 + (d ^ (m & 31))] = kbase[m*Dd + d];
            Vsm[m*32 + d]              = vbase[m*Dd + d];
        }
    }
    float bar0 = dist_bar[0], bar1 = dist_bar[1], bar2 = dist_bar[2], bar3 = dist_bar[3];
    __syncthreads();

    for (int qi = 0; qi < 4; qi++) {
        const int n = n0 + qi*8 + warp;

        float qreg = ql[(b*Nn + n)*Dd + h*32 + lane] * 0.17677669529663687f;

        unsigned okbits = 0;
        float dv[8];
        const int*   mrow = &mask[(b*Nn + n)*Nn];
        const float* drow = (n > 0) ? &dist[(b*(Nn-1) + (n-1))*(Nn-1)] : 0;
        #pragma unroll
        for (int i = 0; i < 8; i++) {
            int m = 32*i + lane;
            if (mrow[m] != 0) okbits |= (1u << i);
            dv[i] = (n > 0 && m > 0) ? drow[m-1] : -1.0f;
        }

        float sb8[8];
        #pragma unroll
        for (int i = 0; i < 8; i++) sb8[i] = 0.0f;
        #pragma unroll
        for (int d = 0; d < 32; d++) {
            float qd = __shfl_sync(0xffffffffu, qreg, d);
            int cc = d ^ lane;
            #pragma unroll
            for (int i = 0; i < 8; i++)
                sb8[i] += qd * Ksm[(32*i + lane)*32 + cc];
        }

        const float* bbase = &bias[((b*Kk)*Nn + n)*Nn];
        #pragma unroll
        for (int kk = 0; kk < 4; kk++) {
            float bar = (kk == 0) ? bar0 : (kk == 1) ? bar1 : (kk == 2) ? bar2 : bar3;
            const float* brow = bbase + kk*Nn*Nn;
            float s[8];
            float mx = -1e30f;
            #pragma unroll
            for (int i = 0; i < 8; i++) {
                int m = 32*i + lane;
                float sv = sb8[i] + brow[m];
                bool ok = ((okbits >> i) & 1u) && (dv[i] < bar);
                s[i] = ok ? sv : -1e12f;
                mx = fmaxf(mx, s[i]);
            }
            #pragma unroll
            for (int off = 16; off > 0; off >>= 1)
                mx = fmaxf(mx, __shfl_xor_sync(0xffffffffu, mx, off));
            float sum = 0.0f;
            #pragma unroll
            for (int i = 0; i < 8; i++) {
                s[i] = __expf(s[i] - mx);
                sum += s[i];
            }
            #pragma unroll
            for (int off = 16; off > 0; off >>= 1)
                sum += __shfl_xor_sync(0xffffffffu, sum, off);
            float inv = 1.0f / sum;
            #pragma unroll
            for (int i = 0; i < 8; i++)
                Psm[(32*i + lane)*4 + kk] = s[i] * inv;
        }
        __syncwarp();

        // AV: lane = dim; pointer-increment, conflict-free
        float a0 = 0.0f, a1 = 0.0f, a2 = 0.0f, a3 = 0.0f;
        const float* pp = Psm;
        const float* vp = Vsm + lane;
        #pragma unroll 8
        for (int m = 0; m < 256; m++) {
            float4 pv = *reinterpret_cast<const float4*>(pp); pp += 4;
            float vv = *vp; vp += 32;
            a0 += pv.x * vv; a1 += pv.y * vv; a2 += pv.z * vv; a3 += pv.w * vv;
        }

        {
            int rsub = h*4 + (lane >> 3);
            int col  = (lane & 7)*256 + n;
            float av[4] = {a0, a1, a2, a3};
            #pragma unroll
            for (int kk = 0; kk < 4; kk++) {
                int row = kk*64 + rsub;
                msg2[(size_t)(b*Nn + row)*KD + col] = av[kk];
            }
        }
        __syncwarp();
    }
}

// ---------------- residual add + LayerNorm (D = 512) ----------------
__global__ void ln_kernel(const float* __restrict__ a,
                          const float* __restrict__ res,
                          const float* __restrict__ g,
                          const float* __restrict__ be,
                          float* __restrict__ out)
{
    const int row = blockIdx.x;
    const int t = threadIdx.x;
    __shared__ float red[256];

    float v0 = a[row*Dd + t]       + res[row*Dd + t];
    float v1 = a[row*Dd + 256 + t] + res[row*Dd + 256 + t];

    red[t] = v0 + v1;
    __syncthreads();
    #pragma unroll
    for (int off = 128; off > 0; off >>= 1) {
        if (t < off) red[t] += red[t + off];
        __syncthreads();
    }
    float mean = red[0] * (1.0f / 512.0f);
    __syncthreads();

    float d0 = v0 - mean, d1 = v1 - mean;
    red[t] = d0*d0 + d1*d1;
    __syncthreads();
    #pragma unroll
    for (int off = 128; off > 0; off >>= 1) {
        if (t < off) red[t] += red[t + off];
        __syncthreads();
    }
    float var = red[0] * (1.0f / 512.0f);
    float rstd = rsqrtf(var + 1e-6f);

    out[row*Dd + t]       = d0 * rstd * g[t]       + be[t];
    out[row*Dd + 256 + t] = d1 * rstd * g[t + 256] + be[t + 256];
}

// ---------------- launch ----------------
extern "C" void kernel_launch(void* const* d_in, const int* in_sizes, int n_in,
                              void* d_out, int out_size)
{
    const float* x         = (const float*)d_in[0];
    const float* dist      = (const float*)d_in[1];
    const float* dist_bar  = (const float*)d_in[2];
    const float* attn_bias = (const float*)d_in[3];
    const int*   mask      = (const int*)  d_in[4];
    // d_in[5] = num_heads (compile-time)
    const float* Wq = (const float*)d_in[6],  *bq = (const float*)d_in[7];
    const float* Wk = (const float*)d_in[8],  *bk = (const float*)d_in[9];
    const float* Wv = (const float*)d_in[10], *bv = (const float*)d_in[11];
    const float* W1 = (const float*)d_in[12], *b1 = (const float*)d_in[13];
    const float* W2 = (const float*)d_in[14], *b2 = (const float*)d_in[15];
    const float* g1 = (const float*)d_in[16], *be1 = (const float*)d_in[17];
    const float* Wf1 = (const float*)d_in[18], *bf1 = (const float*)d_in[19];
    const float* Wf2 = (const float*)d_in[20], *bf2 = (const float*)d_in[21];
    const float* g2 = (const float*)d_in[22], *be2 = (const float*)d_in[23];
    float* out = (float*)d_out;

    float *qlin, *klin, *vlin, *msg2, *t1, *hb, *yb, *t2, *fb;
    cudaGetSymbolAddress((void**)&qlin, g_qlin);
    cudaGetSymbolAddress((void**)&klin, g_klin);
    cudaGetSymbolAddress((void**)&vlin, g_vlin);
    cudaGetSymbolAddress((void**)&msg2, g_msg2);
    cudaGetSymbolAddress((void**)&t1,   g_t1);
    cudaGetSymbolAddress((void**)&hb,   g_h);
    cudaGetSymbolAddress((void**)&yb,   g_y);
    cudaGetSymbolAddress((void**)&t2,   g_t2);
    cudaGetSymbolAddress((void**)&fb,   g_f);

    dim3 blk(256);
    dim3 g512(Dd/64,  Mrows/128);   // (8, 16)
    dim3 gFFN(FFNs/64, Mrows/128);  // (32, 16)

    // QKV: fp32 FFMA (precision headroom for attention)
    gemm_kernel<0><<<g512, blk>>>(x, Wq, bq, qlin, Dd, Dd);
    gemm_kernel<0><<<g512, blk>>>(x, Wk, bk, klin, Dd, Dd);
    gemm_kernel<0><<<g512, blk>>>(x, Wv, bv, vlin, Dd, Dd);

    // fused attention: 96KB dynamic smem (K 32KB + V 32KB + 8 warps x 4KB p)
    const int ATTN_SMEM = 98304;
    cudaFuncSetAttribute(attn_kernel,
                         cudaFuncAttributeMaxDynamicSharedMemorySize, ATTN_SMEM);
    dim3 ga(Bb*Hh, Nn/32);          // (128, 8)
    attn_kernel<<<ga, blk, ATTN_SMEM>>>(qlin, klin, vlin, attn_bias, mask,
                                        dist, dist_bar, msg2);

    // big GEMMs: tf32 tensor cores, software-pipelined
    gemm_tf32_kernel<1><<<g512, blk>>>(msg2, W1, b1, t1, KD, Dd);
    gemm_tf32_kernel<0><<<g512, blk>>>(t1,   W2, b2, hb, Dd, Dd);
    ln_kernel<<<Mrows, blk>>>(hb, x, g1, be1, yb);

    gemm_tf32_kernel<2><<<gFFN, blk>>>(yb, Wf1, bf1, t2, Dd, FFNs);
    gemm_tf32_kernel<0><<<g512, blk>>>(t2, Wf2, bf2, fb, FFNs, Dd);
    ln_kernel<<<Mrows, blk>>>(fb, yb, g2, be2, out);
}

// round 15
// speedup vs baseline: 2.6390x; 1.1117x over previous
#include <cuda_runtime.h>
#include <cuda_fp16.h>
#include <math.h>
#include <stdint.h>

// Problem constants
#define Bb   8
#define Nn   256
#define Dd   512
#define Hh   16
#define Kk   4
#define FFNs 2048
#define Mrows (Bb*Nn)          // 2048
#define KD   (Kk*Dd)           // 2048

// ---------------- scratch ----------------
__device__ float g_qlin[Mrows*Dd];
__device__ float g_klin[Mrows*Dd];
__device__ float g_vlin[Mrows*Dd];
__device__ float g_msg2[Mrows*KD];
__device__ float g_t1[Mrows*Dd];
__device__ float g_h [Mrows*Dd];
__device__ float g_y [Mrows*Dd];
__device__ float g_t2[Mrows*FFNs];
__device__ float g_f [Mrows*Dd];

// ---------------- tf32 tensor-core GEMM, software-pipelined ----------------
// BM=128, BN=64, BK=16, 256 threads = 8 warps (4 M x 2 N), warp tile 32x32.
// Double-buffered smem; per iter: issue next-tile LDG, run MMAs on current
// buffer, then CVT+STS the in-flight data (overlaps global latency with MMA).
__device__ __forceinline__ uint32_t f2tf32(float x) {
    uint32_t u;
    asm("cvt.rna.tf32.f32 %0, %1;" : "=r"(u) : "f"(x));
    return u;
}

template<int ACT>
__global__ void __launch_bounds__(256, 2)
gemm_tf32_kernel(const float* __restrict__ A,
                 const float* __restrict__ W,
                 const float* __restrict__ bias,
                 float* __restrict__ C,
                 int Kdim, int Ncols)
{
    __shared__ uint32_t As[2][128][17];
    __shared__ uint32_t Ws[2][16][68];

    const int tid  = threadIdx.x;
    const int warp = tid >> 5;
    const int lane = tid & 31;
    const int wm = warp & 3;
    const int wn = warp >> 2;
    const int g  = lane >> 2;
    const int tg = lane & 3;

    const int rowBase = blockIdx.y * 128;
    const int colBase = blockIdx.x * 64;

    const int a0r = tid >> 2,          a0c = (tid & 3) * 4;
    const int a1r = (tid + 256) >> 2,  a1c = a0c;
    const int wr  = tid >> 4,          wc  = (tid & 15) * 4;

    float c[2][4][4];
    #pragma unroll
    for (int i = 0; i < 2; i++)
        #pragma unroll
        for (int j = 0; j < 4; j++)
            #pragma unroll
            for (int q = 0; q < 4; q++) c[i][j][q] = 0.0f;

    float4 va0, va1, vw;
    auto gload = [&](int k0) {
        va0 = *reinterpret_cast<const float4*>(&A[(rowBase + a0r) * Kdim + k0 + a0c]);
        va1 = *reinterpret_cast<const float4*>(&A[(rowBase + a1r) * Kdim + k0 + a1c]);
        vw  = *reinterpret_cast<const float4*>(&W[(k0 + wr) * Ncols + colBase + wc]);
    };
    auto sstore = [&](int buf) {
        As[buf][a0r][a0c+0] = f2tf32(va0.x); As[buf][a0r][a0c+1] = f2tf32(va0.y);
        As[buf][a0r][a0c+2] = f2tf32(va0.z); As[buf][a0r][a0c+3] = f2tf32(va0.w);
        As[buf][a1r][a1c+0] = f2tf32(va1.x); As[buf][a1r][a1c+1] = f2tf32(va1.y);
        As[buf][a1r][a1c+2] = f2tf32(va1.z); As[buf][a1r][a1c+3] = f2tf32(va1.w);
        Ws[buf][wr][wc+0] = f2tf32(vw.x); Ws[buf][wr][wc+1] = f2tf32(vw.y);
        Ws[buf][wr][wc+2] = f2tf32(vw.z); Ws[buf][wr][wc+3] = f2tf32(vw.w);
    };

    const int nIter = Kdim >> 4;
    gload(0);
    sstore(0);
    __syncthreads();

    for (int it = 0; it < nIter; it++) {
        const int buf = it & 1;
        if (it + 1 < nIter) gload((it + 1) << 4);

        #pragma unroll
        for (int ks = 0; ks < 16; ks += 8) {
            uint32_t a[2][4];
            #pragma unroll
            for (int ma = 0; ma < 2; ma++) {
                int r = wm*32 + ma*16;
                a[ma][0] = As[buf][r + g    ][ks + tg    ];
                a[ma][1] = As[buf][r + g + 8][ks + tg    ];
                a[ma][2] = As[buf][r + g    ][ks + tg + 4];
                a[ma][3] = As[buf][r + g + 8][ks + tg + 4];
            }
            uint32_t bfr[4][2];
            #pragma unroll
            for (int na = 0; na < 4; na++) {
                int n = wn*32 + na*8 + g;
                bfr[na][0] = Ws[buf][ks + tg    ][n];
                bfr[na][1] = Ws[buf][ks + tg + 4][n];
            }
            #pragma unroll
            for (int ma = 0; ma < 2; ma++)
                #pragma unroll
                for (int na = 0; na < 4; na++) {
                    asm volatile(
                        "mma.sync.aligned.m16n8k8.row.col.f32.tf32.tf32.f32 "
                        "{%0,%1,%2,%3}, {%4,%5,%6,%7}, {%8,%9}, {%0,%1,%2,%3};"
                        : "+f"(c[ma][na][0]), "+f"(c[ma][na][1]),
                          "+f"(c[ma][na][2]), "+f"(c[ma][na][3])
                        : "r"(a[ma][0]), "r"(a[ma][1]), "r"(a[ma][2]), "r"(a[ma][3]),
                          "r"(bfr[na][0]), "r"(bfr[na][1]));
                }
        }

        if (it + 1 < nIter) sstore(buf ^ 1);
        __syncthreads();
    }

    // epilogue: c0:(g,2tg) c1:(g,2tg+1) c2:(g+8,2tg) c3:(g+8,2tg+1)
    #pragma unroll
    for (int ma = 0; ma < 2; ma++) {
        int row0 = rowBase + wm*32 + ma*16 + g;
        #pragma unroll
        for (int na = 0; na < 4; na++) {
            int col = colBase + wn*32 + na*8 + tg*2;
            float b0 = bias[col], b1 = bias[col+1];
            float v00 = c[ma][na][0] + b0, v01 = c[ma][na][1] + b1;
            float v10 = c[ma][na][2] + b0, v11 = c[ma][na][3] + b1;
            if (ACT == 1) {
                v00 = v00 / (1.0f + expf(-v00)); v01 = v01 / (1.0f + expf(-v01));
                v10 = v10 / (1.0f + expf(-v10)); v11 = v11 / (1.0f + expf(-v11));
            } else if (ACT == 2) {
                const float is2 = 0.70710678118654752f;
                v00 = 0.5f*v00*(1.0f+erff(v00*is2)); v01 = 0.5f*v01*(1.0f+erff(v01*is2));
                v10 = 0.5f*v10*(1.0f+erff(v10*is2)); v11 = 0.5f*v11*(1.0f+erff(v11*is2));
            }
            C[ row0      * Ncols + col    ] = v00;
            C[ row0      * Ncols + col + 1] = v01;
            C[(row0 + 8) * Ncols + col    ] = v10;
            C[(row0 + 8) * Ncols + col + 1] = v11;
        }
    }
}

// ---------------- fused multi-scale attention ----------------
// grid = (B*H = 128, N/32 = 8), block = 256 (8 warps). K swizzled, V plain.
// Warp-per-query; all 4 scale softmaxes computed into registers, then p
// packed as 2x half2 (8B/key) into per-warp smem -> AV pass reads half the
// bytes of the float4 variant (L1 was 81.9% = LDS-throughput-bound).
// Scatter into torch-faithful scrambled msg2:
//   row = b*256 + (kk*16+h)*4 + (d>>3), col = (d&7)*256 + n.
__global__ void __launch_bounds__(256, 2)
attn_kernel(const float* __restrict__ ql,
            const float* __restrict__ kl,
            const float* __restrict__ vl,
            const float* __restrict__ bias,
            const int*   __restrict__ mask,
            const float* __restrict__ dist,
            const float* __restrict__ dist_bar,
            float* __restrict__ msg2)
{
    extern __shared__ float smemf[];
    float* Ksm = smemf;                // [256][32] swizzled: col = d ^ (m&31)
    float* Vsm = smemf + 8192;         // [256][32] plain
    const int tid  = threadIdx.x;
    const int warp = tid >> 5;
    const int lane = tid & 31;
    __half* Psm = reinterpret_cast<__half*>(smemf + 16384) + warp * 1024; // 2KB/warp

    const int bh = blockIdx.x;
    const int b  = bh >> 4;
    const int h  = bh & 15;
    const int n0 = blockIdx.y * 32;

    {
        const float* kbase = &kl[(b*Nn)*Dd + h*32];
        const float* vbase = &vl[(b*Nn)*Dd + h*32];
        #pragma unroll
        for (int it = 0; it < 32; it++) {
            int idx = tid + it * 256;
            int m = idx >> 5, d = idx & 31;
            Ksm[m*32 + (d ^ (m & 31))] = kbase[m*Dd + d];
            Vsm[m*32 + d]              = vbase[m*Dd + d];
        }
    }
    float bar0 = dist_bar[0], bar1 = dist_bar[1], bar2 = dist_bar[2], bar3 = dist_bar[3];
    __syncthreads();

    for (int qi = 0; qi < 4; qi++) {
        const int n = n0 + qi*8 + warp;

        float qreg = ql[(b*Nn + n)*Dd + h*32 + lane] * 0.17677669529663687f;

        unsigned okbits = 0;
        float dv[8];
        const int*   mrow = &mask[(b*Nn + n)*Nn];
        const float* drow = (n > 0) ? &dist[(b*(Nn-1) + (n-1))*(Nn-1)] : 0;
        #pragma unroll
        for (int i = 0; i < 8; i++) {
            int m = 32*i + lane;
            if (mrow[m] != 0) okbits |= (1u << i);
            dv[i] = (n > 0 && m > 0) ? drow[m-1] : -1.0f;
        }

        float sb8[8];
        #pragma unroll
        for (int i = 0; i < 8; i++) sb8[i] = 0.0f;
        #pragma unroll
        for (int d = 0; d < 32; d++) {
            float qd = __shfl_sync(0xffffffffu, qreg, d);
            int cc = d ^ lane;
            #pragma unroll
            for (int i = 0; i < 8; i++)
                sb8[i] += qd * Ksm[(32*i + lane)*32 + cc];
        }

        // 4 scale softmaxes -> p4 in registers
        float p4[4][8];
        const float* bbase = &bias[((b*Kk)*Nn + n)*Nn];
        #pragma unroll
        for (int kk = 0; kk < 4; kk++) {
            float bar = (kk == 0) ? bar0 : (kk == 1) ? bar1 : (kk == 2) ? bar2 : bar3;
            const float* brow = bbase + kk*Nn*Nn;
            float s[8];
            float mx = -1e30f;
            #pragma unroll
            for (int i = 0; i < 8; i++) {
                int m = 32*i + lane;
                float sv = sb8[i] + brow[m];
                bool ok = ((okbits >> i) & 1u) && (dv[i] < bar);
                s[i] = ok ? sv : -1e12f;
                mx = fmaxf(mx, s[i]);
            }
            #pragma unroll
            for (int off = 16; off > 0; off >>= 1)
                mx = fmaxf(mx, __shfl_xor_sync(0xffffffffu, mx, off));
            float sum = 0.0f;
            #pragma unroll
            for (int i = 0; i < 8; i++) {
                s[i] = __expf(s[i] - mx);
                sum += s[i];
            }
            #pragma unroll
            for (int off = 16; off > 0; off >>= 1)
                sum += __shfl_xor_sync(0xffffffffu, sum, off);
            float inv = 1.0f / sum;
            #pragma unroll
            for (int i = 0; i < 8; i++) p4[kk][i] = s[i] * inv;
        }

        // pack 4 scales as 2x half2, one 8B store per key
        #pragma unroll
        for (int i = 0; i < 8; i++) {
            __half2 h01 = __floats2half2_rn(p4[0][i], p4[1][i]);
            __half2 h23 = __floats2half2_rn(p4[2][i], p4[3][i]);
            uint2 u;
            u.x = *reinterpret_cast<uint32_t*>(&h01);
            u.y = *reinterpret_cast<uint32_t*>(&h23);
            *reinterpret_cast<uint2*>(Psm + (32*i + lane)*4) = u;
        }
        __syncwarp();

        // AV: lane = dim; 8B broadcast p + 4B V per key
        float a0 = 0.0f, a1 = 0.0f, a2 = 0.0f, a3 = 0.0f;
        const uint2* pp = reinterpret_cast<const uint2*>(Psm);
        const float* vp = Vsm + lane;
        #pragma unroll 8
        for (int m = 0; m < 256; m++) {
            uint2 u = pp[m];
            float2 p01 = __half22float2(*reinterpret_cast<__half2*>(&u.x));
            float2 p23 = __half22float2(*reinterpret_cast<__half2*>(&u.y));
            float vv = *vp; vp += 32;
            a0 += p01.x * vv; a1 += p01.y * vv; a2 += p23.x * vv; a3 += p23.y * vv;
        }

        {
            int rsub = h*4 + (lane >> 3);
            int col  = (lane & 7)*256 + n;
            float av[4] = {a0, a1, a2, a3};
            #pragma unroll
            for (int kk = 0; kk < 4; kk++) {
                int row = kk*64 + rsub;
                msg2[(size_t)(b*Nn + row)*KD + col] = av[kk];
            }
        }
        __syncwarp();
    }
}

// ---------------- residual add + LayerNorm (D = 512) ----------------
__global__ void ln_kernel(const float* __restrict__ a,
                          const float* __restrict__ res,
                          const float* __restrict__ g,
                          const float* __restrict__ be,
                          float* __restrict__ out)
{
    const int row = blockIdx.x;
    const int t = threadIdx.x;
    __shared__ float red[256];

    float v0 = a[row*Dd + t]       + res[row*Dd + t];
    float v1 = a[row*Dd + 256 + t] + res[row*Dd + 256 + t];

    red[t] = v0 + v1;
    __syncthreads();
    #pragma unroll
    for (int off = 128; off > 0; off >>= 1) {
        if (t < off) red[t] += red[t + off];
        __syncthreads();
    }
    float mean = red[0] * (1.0f / 512.0f);
    __syncthreads();

    float d0 = v0 - mean, d1 = v1 - mean;
    red[t] = d0*d0 + d1*d1;
    __syncthreads();
    #pragma unroll
    for (int off = 128; off > 0; off >>= 1) {
        if (t < off) red[t] += red[t + off];
        __syncthreads();
    }
    float var = red[0] * (1.0f / 512.0f);
    float rstd = rsqrtf(var + 1e-6f);

    out[row*Dd + t]       = d0 * rstd * g[t]       + be[t];
    out[row*Dd + 256 + t] = d1 * rstd * g[t + 256] + be[t + 256];
}

// ---------------- launch ----------------
extern "C" void kernel_launch(void* const* d_in, const int* in_sizes, int n_in,
                              void* d_out, int out_size)
{
    const float* x         = (const float*)d_in[0];
    const float* dist      = (const float*)d_in[1];
    const float* dist_bar  = (const float*)d_in[2];
    const float* attn_bias = (const float*)d_in[3];
    const int*   mask      = (const int*)  d_in[4];
    // d_in[5] = num_heads (compile-time)
    const float* Wq = (const float*)d_in[6],  *bq = (const float*)d_in[7];
    const float* Wk = (const float*)d_in[8],  *bk = (const float*)d_in[9];
    const float* Wv = (const float*)d_in[10], *bv = (const float*)d_in[11];
    const float* W1 = (const float*)d_in[12], *b1 = (const float*)d_in[13];
    const float* W2 = (const float*)d_in[14], *b2 = (const float*)d_in[15];
    const float* g1 = (const float*)d_in[16], *be1 = (const float*)d_in[17];
    const float* Wf1 = (const float*)d_in[18], *bf1 = (const float*)d_in[19];
    const float* Wf2 = (const float*)d_in[20], *bf2 = (const float*)d_in[21];
    const float* g2 = (const float*)d_in[22], *be2 = (const float*)d_in[23];
    float* out = (float*)d_out;

    float *qlin, *klin, *vlin, *msg2, *t1, *hb, *yb, *t2, *fb;
    cudaGetSymbolAddress((void**)&qlin, g_qlin);
    cudaGetSymbolAddress((void**)&klin, g_klin);
    cudaGetSymbolAddress((void**)&vlin, g_vlin);
    cudaGetSymbolAddress((void**)&msg2, g_msg2);
    cudaGetSymbolAddress((void**)&t1,   g_t1);
    cudaGetSymbolAddress((void**)&hb,   g_h);
    cudaGetSymbolAddress((void**)&yb,   g_y);
    cudaGetSymbolAddress((void**)&t2,   g_t2);
    cudaGetSymbolAddress((void**)&fb,   g_f);

    dim3 blk(256);
    dim3 g512(Dd/64,  Mrows/128);   // (8, 16)
    dim3 gFFN(FFNs/64, Mrows/128);  // (32, 16)

    // QKV: tf32 tensor cores (same proven kernel as the big GEMMs)
    gemm_tf32_kernel<0><<<g512, blk>>>(x, Wq, bq, qlin, Dd, Dd);
    gemm_tf32_kernel<0><<<g512, blk>>>(x, Wk, bk, klin, Dd, Dd);
    gemm_tf32_kernel<0><<<g512, blk>>>(x, Wv, bv, vlin, Dd, Dd);

    // fused attention: 80KB dynamic smem (K 32KB + V 32KB + 8 warps x 2KB p16)
    const int ATTN_SMEM = 81920;
    cudaFuncSetAttribute(attn_kernel,
                         cudaFuncAttributeMaxDynamicSharedMemorySize, ATTN_SMEM);
    dim3 ga(Bb*Hh, Nn/32);          // (128, 8)
    attn_kernel<<<ga, blk, ATTN_SMEM>>>(qlin, klin, vlin, attn_bias, mask,
                                        dist, dist_bar, msg2);

    // big GEMMs: tf32 tensor cores, software-pipelined
    gemm_tf32_kernel<1><<<g512, blk>>>(msg2, W1, b1, t1, KD, Dd);
    gemm_tf32_kernel<0><<<g512, blk>>>(t1,   W2, b2, hb, Dd, Dd);
    ln_kernel<<<Mrows, blk>>>(hb, x, g1, be1, yb);

    gemm_tf32_kernel<2><<<gFFN, blk>>>(yb, Wf1, bf1, t2, Dd, FFNs);
    gemm_tf32_kernel<0><<<g512, blk>>>(t2, Wf2, bf2, fb, FFNs, Dd);
    ln_kernel<<<Mrows, blk>>>(fb, yb, g2, be2, out);
}